// round 1
// baseline (speedup 1.0000x reference)
#include <cuda_runtime.h>
#include <math.h>

#define BB 32
#define TT 1024
#define CC 256
#define HH 64

#define QT 128   // query rows per CTA
#define KT 32    // keys per smem tile

// scratch for projected q,k,v  (3 * 8 MB)
__device__ float g_q[BB * TT * HH];
__device__ float g_k[BB * TT * HH];
__device__ float g_v[BB * TT * HH];

// ---------------------------------------------------------------------------
// Projection: one CTA per (b,t) row. 192 threads: tid>>6 selects q/k/v matrix,
// tid&63 selects the output head-dim. x row staged in smem (broadcast reads),
// W columns coalesced across the warp, L2-resident (64 KB each).
// ---------------------------------------------------------------------------
__global__ __launch_bounds__(192) void proj_kernel(
    const float* __restrict__ x,
    const float* __restrict__ Wq,
    const float* __restrict__ Wk,
    const float* __restrict__ Wv)
{
    __shared__ float xs[CC];
    const int bt = blockIdx.x;
    const float* xrow = x + (size_t)bt * CC;
    for (int i = threadIdx.x; i < CC; i += 192) xs[i] = xrow[i];
    __syncthreads();

    const int h     = threadIdx.x & 63;
    const int which = threadIdx.x >> 6;       // warp-uniform (192 = 6 warps)
    const float* W  = (which == 0) ? Wq : (which == 1) ? Wk : Wv;

    float acc = 0.f;
#pragma unroll 8
    for (int c = 0; c < CC; ++c)
        acc = fmaf(xs[c], W[c * HH + h], acc);

    float* dst = (which == 0) ? g_q : (which == 1) ? g_k : g_v;
    dst[(size_t)bt * HH + h] = acc;
}

// ---------------------------------------------------------------------------
// Flash attention: grid (T/QT, B). Each thread owns one query row.
// q + accumulator live in registers; K/V tiles (KT x H) in smem, all smem
// reads are uniform across the CTA (broadcast, conflict-free). Per-thread
// score row lives in padded smem (stride KT+1 -> conflict-free).
// ---------------------------------------------------------------------------
__global__ __launch_bounds__(QT) void attn_kernel(
    float* __restrict__ out, float scale)
{
    __shared__ float Ksh[KT][HH];            // 8 KB
    __shared__ float Vsh[KT][HH];            // 8 KB
    __shared__ float Ssh[QT * (KT + 1)];     // 16.5 KB, padded vs bank conflicts

    const int b     = blockIdx.y;
    const int qtile = blockIdx.x;
    const int tid   = threadIdx.x;
    const int t     = qtile * QT + tid;      // this thread's query row

    // load q row (256 B aligned) into registers
    float q[HH];
    {
        const float4* qp = (const float4*)(g_q + ((size_t)b * TT + t) * HH);
#pragma unroll
        for (int i = 0; i < HH / 4; ++i) {
            float4 v = qp[i];
            q[4 * i + 0] = v.x; q[4 * i + 1] = v.y;
            q[4 * i + 2] = v.z; q[4 * i + 3] = v.w;
        }
    }

    float acc[HH];
#pragma unroll
    for (int d = 0; d < HH; ++d) acc[d] = 0.f;
    float m = -1e30f, l = 0.f;

    float* srow = Ssh + tid * (KT + 1);

    const int ntiles = (qtile * QT + QT) / KT;   // keys up to end of this q-tile
    for (int kt = 0; kt < ntiles; ++kt) {
        const int kbase = kt * KT;

        // cooperative tile load: KT*HH = 2048 floats per array, float4,
        // 128 threads -> 4 vec-loads per thread per array
        {
            const float4* kp = (const float4*)(g_k + ((size_t)b * TT + kbase) * HH);
            const float4* vp = (const float4*)(g_v + ((size_t)b * TT + kbase) * HH);
            float4* ks = (float4*)&Ksh[0][0];
            float4* vs = (float4*)&Vsh[0][0];
#pragma unroll
            for (int i = 0; i < (KT * HH) / (QT * 4); ++i) {
                int idx = i * QT + tid;
                ks[idx] = kp[idx];
                vs[idx] = vp[idx];
            }
        }
        __syncthreads();

        if (kbase <= t) {                     // tile has at least one valid key
            // ---- scores ----
            float mt = -1e30f;
            for (int j = 0; j < KT; ++j) {
                float s = 0.f;
#pragma unroll
                for (int d = 0; d < HH; ++d)
                    s = fmaf(q[d], Ksh[j][d], s);
                s *= scale;
                if (kbase + j > t) s = -1e30f;   // causal mask
                srow[j] = s;
                mt = fmaxf(mt, s);
            }

            // ---- online softmax rescale ----
            const float mnew = fmaxf(m, mt);
            const float corr = __expf(m - mnew);   // exp(-1e30-x) -> 0 on first tile
            l *= corr;
#pragma unroll
            for (int d = 0; d < HH; ++d) acc[d] *= corr;

            // ---- accumulate P @ V ----
            for (int j = 0; j < KT; ++j) {
                const float p = __expf(srow[j] - mnew);
                l += p;
#pragma unroll
                for (int d = 0; d < HH; ++d)
                    acc[d] = fmaf(p, Vsh[j][d], acc[d]);
            }
            m = mnew;
        }
        __syncthreads();
    }

    const float inv = 1.f / l;   // l >= exp(0 contribution): key s=0 always valid
    float4* op = (float4*)(out + ((size_t)b * TT + t) * HH);
#pragma unroll
    for (int i = 0; i < HH / 4; ++i) {
        float4 v;
        v.x = acc[4 * i + 0] * inv; v.y = acc[4 * i + 1] * inv;
        v.z = acc[4 * i + 2] * inv; v.w = acc[4 * i + 3] * inv;
        op[i] = v;
    }
}

// ---------------------------------------------------------------------------
extern "C" void kernel_launch(void* const* d_in, const int* in_sizes, int n_in,
                              void* d_out, int out_size)
{
    const float* x  = (const float*)d_in[0];
    const float* Wq = (const float*)d_in[1];
    const float* Wk = (const float*)d_in[2];
    const float* Wv = (const float*)d_in[3];
    float* out = (float*)d_out;

    const float scale = (float)pow(256.0, -0.666);   // C^-0.666, host-side double

    proj_kernel<<<BB * TT, 192>>>(x, Wq, Wk, Wv);

    dim3 grid(TT / QT, BB);
    attn_kernel<<<grid, QT>>>(out, scale);
}

// round 2
// speedup vs baseline: 1.2526x; 1.2526x over previous
#include <cuda_runtime.h>
#include <math.h>

#define BB 32
#define TT 1024
#define CC 256
#define HH 64

#define QT 64    // query rows per CTA (1 thread = 1 query row)
#define KT 32    // keys per smem tile
#define PR 4     // rows per proj CTA

// scratch for projected q,k,v  (3 * 8 MB)
__device__ float g_q[BB * TT * HH];
__device__ float g_k[BB * TT * HH];
__device__ float g_v[BB * TT * HH];

// ---------------------------------------------------------------------------
// Projection: one CTA per PR (b,t) rows. 192 threads: tid>>6 selects q/k/v,
// tid&63 selects the head-dim column. Each thread carries PR independent
// accumulators sharing one W load per c -> 4-way ILP, W traffic /4.
// ---------------------------------------------------------------------------
__global__ __launch_bounds__(192) void proj_kernel(
    const float* __restrict__ x,
    const float* __restrict__ Wq,
    const float* __restrict__ Wk,
    const float* __restrict__ Wv)
{
    __shared__ float xs[PR][CC];
    const int bt0 = blockIdx.x * PR;
    {
        const float4* xp = (const float4*)(x + (size_t)bt0 * CC);
        float4* xsp = (float4*)&xs[0][0];
        // PR*CC/4 = 256 float4 over 192 threads
        for (int i = threadIdx.x; i < PR * CC / 4; i += 192) xsp[i] = xp[i];
    }
    __syncthreads();

    const int h     = threadIdx.x & 63;
    const int which = threadIdx.x >> 6;       // warp-uniform (192 = 6 warps)
    const float* W  = (which == 0) ? Wq : (which == 1) ? Wk : Wv;

    float a0 = 0.f, a1 = 0.f, a2 = 0.f, a3 = 0.f;
#pragma unroll 4
    for (int c = 0; c < CC; ++c) {
        const float w = W[c * HH + h];
        a0 = fmaf(xs[0][c], w, a0);
        a1 = fmaf(xs[1][c], w, a1);
        a2 = fmaf(xs[2][c], w, a2);
        a3 = fmaf(xs[3][c], w, a3);
    }

    float* dst = (which == 0) ? g_q : (which == 1) ? g_k : g_v;
    dst[(size_t)(bt0 + 0) * HH + h] = a0;
    dst[(size_t)(bt0 + 1) * HH + h] = a1;
    dst[(size_t)(bt0 + 2) * HH + h] = a2;
    dst[(size_t)(bt0 + 3) * HH + h] = a3;
}

// ---------------------------------------------------------------------------
// Flash attention: grid (T/QT, B), QT threads, 1 thread = 1 query row.
// Score loop processes 4 keys concurrently (4 independent FMA chains) with
// float4 smem loads. PV loop has ILP-64 across the accumulator array.
// ---------------------------------------------------------------------------
__global__ __launch_bounds__(QT) void attn_kernel(
    float* __restrict__ out, float scale)
{
    __shared__ float Ksh[KT][HH];            // 8 KB
    __shared__ float Vsh[KT][HH];            // 8 KB
    __shared__ float Ssh[QT * (KT + 1)];     // 8.25 KB padded

    const int b     = blockIdx.y;
    const int qtile = blockIdx.x;
    const int tid   = threadIdx.x;
    const int t     = qtile * QT + tid;

    float q[HH];
    {
        const float4* qp = (const float4*)(g_q + ((size_t)b * TT + t) * HH);
#pragma unroll
        for (int i = 0; i < HH / 4; ++i) {
            float4 v = qp[i];
            q[4 * i + 0] = v.x; q[4 * i + 1] = v.y;
            q[4 * i + 2] = v.z; q[4 * i + 3] = v.w;
        }
    }

    float acc[HH];
#pragma unroll
    for (int d = 0; d < HH; ++d) acc[d] = 0.f;
    float m = -1e30f, l = 0.f;

    float* srow = Ssh + tid * (KT + 1);

    const int ntiles = (qtile * QT + QT) / KT;
    for (int kt = 0; kt < ntiles; ++kt) {
        const int kbase = kt * KT;

        // cooperative K/V tile load: KT*HH/4 = 512 float4 per array, 64 threads
        {
            const float4* kp = (const float4*)(g_k + ((size_t)b * TT + kbase) * HH);
            const float4* vp = (const float4*)(g_v + ((size_t)b * TT + kbase) * HH);
            float4* ks = (float4*)&Ksh[0][0];
            float4* vs = (float4*)&Vsh[0][0];
#pragma unroll
            for (int i = 0; i < (KT * HH) / (QT * 4); ++i) {
                int idx = i * QT + tid;
                ks[idx] = kp[idx];
                vs[idx] = vp[idx];
            }
        }
        __syncthreads();

        if (kbase <= t) {
            // ---- scores: 4 keys at a time, 4 independent FMA chains ----
            float mt = -1e30f;
#pragma unroll
            for (int j0 = 0; j0 < KT; j0 += 4) {
                float s0 = 0.f, s1 = 0.f, s2 = 0.f, s3 = 0.f;
#pragma unroll
                for (int d = 0; d < HH; d += 4) {
                    const float4 k0 = *(const float4*)&Ksh[j0 + 0][d];
                    const float4 k1 = *(const float4*)&Ksh[j0 + 1][d];
                    const float4 k2 = *(const float4*)&Ksh[j0 + 2][d];
                    const float4 k3 = *(const float4*)&Ksh[j0 + 3][d];
                    s0 = fmaf(q[d], k0.x, s0); s0 = fmaf(q[d+1], k0.y, s0);
                    s0 = fmaf(q[d+2], k0.z, s0); s0 = fmaf(q[d+3], k0.w, s0);
                    s1 = fmaf(q[d], k1.x, s1); s1 = fmaf(q[d+1], k1.y, s1);
                    s1 = fmaf(q[d+2], k1.z, s1); s1 = fmaf(q[d+3], k1.w, s1);
                    s2 = fmaf(q[d], k2.x, s2); s2 = fmaf(q[d+1], k2.y, s2);
                    s2 = fmaf(q[d+2], k2.z, s2); s2 = fmaf(q[d+3], k2.w, s2);
                    s3 = fmaf(q[d], k3.x, s3); s3 = fmaf(q[d+1], k3.y, s3);
                    s3 = fmaf(q[d+2], k3.z, s3); s3 = fmaf(q[d+3], k3.w, s3);
                }
                s0 *= scale; s1 *= scale; s2 *= scale; s3 *= scale;
                if (kbase + j0 + 0 > t) s0 = -1e30f;
                if (kbase + j0 + 1 > t) s1 = -1e30f;
                if (kbase + j0 + 2 > t) s2 = -1e30f;
                if (kbase + j0 + 3 > t) s3 = -1e30f;
                srow[j0 + 0] = s0; srow[j0 + 1] = s1;
                srow[j0 + 2] = s2; srow[j0 + 3] = s3;
                mt = fmaxf(mt, fmaxf(fmaxf(s0, s1), fmaxf(s2, s3)));
            }

            // ---- online softmax rescale ----
            const float mnew = fmaxf(m, mt);
            const float corr = __expf(m - mnew);
            l *= corr;
#pragma unroll
            for (int d = 0; d < HH; ++d) acc[d] *= corr;

            // ---- P @ V (ILP-64 across acc) ----
            for (int j = 0; j < KT; ++j) {
                const float p = __expf(srow[j] - mnew);
                l += p;
#pragma unroll
                for (int d = 0; d < HH; ++d)
                    acc[d] = fmaf(p, Vsh[j][d], acc[d]);
            }
            m = mnew;
        }
        __syncthreads();
    }

    const float inv = 1.f / l;
    float4* op = (float4*)(out + ((size_t)b * TT + t) * HH);
#pragma unroll
    for (int i = 0; i < HH / 4; ++i) {
        float4 v;
        v.x = acc[4 * i + 0] * inv; v.y = acc[4 * i + 1] * inv;
        v.z = acc[4 * i + 2] * inv; v.w = acc[4 * i + 3] * inv;
        op[i] = v;
    }
}

// ---------------------------------------------------------------------------
extern "C" void kernel_launch(void* const* d_in, const int* in_sizes, int n_in,
                              void* d_out, int out_size)
{
    const float* x  = (const float*)d_in[0];
    const float* Wq = (const float*)d_in[1];
    const float* Wk = (const float*)d_in[2];
    const float* Wv = (const float*)d_in[3];
    float* out = (float*)d_out;

    const float scale = (float)pow(256.0, -0.666);

    proj_kernel<<<(BB * TT) / PR, 192>>>(x, Wq, Wk, Wv);

    dim3 grid(TT / QT, BB);
    attn_kernel<<<grid, QT>>>(out, scale);
}

// round 3
// speedup vs baseline: 1.8534x; 1.4797x over previous
#include <cuda_runtime.h>
#include <math.h>

#define BB 32
#define TT 1024
#define CC 256
#define HH 64

// ---------------- attention tiling ----------------
#define QT 64           // q rows per CTA
#define KT 64           // keys per tile
#define QSTR 68         // padded strides (floats)
#define KSTR 68
#define VSTR 68
#define PSTR 68
#define ATT_SMEM ((QT*QSTR + KT*KSTR + KT*VSTR + QT*PSTR) * 4)   // 69632 B

// ---------------- projection tiling ----------------
#define PRT 64          // rows per proj CTA
#define PKC 32          // k-chunk

// scratch for projected q,k,v
__device__ float g_q[BB * TT * HH];
__device__ float g_k[BB * TT * HH];
__device__ float g_v[BB * TT * HH];

// ---------------------------------------------------------------------------
// Projection GEMM: X[32768,256] @ W[256,64] (3 matrices via blockIdx.y).
// CTA 128 threads computes a 64x64 tile; each thread a 4x8 micro-tile.
// ---------------------------------------------------------------------------
__global__ __launch_bounds__(128) void proj_kernel(
    const float* __restrict__ x,
    const float* __restrict__ Wq,
    const float* __restrict__ Wk,
    const float* __restrict__ Wv)
{
    __shared__ float Xs[PRT][PKC + 4];   // 64 x 36
    __shared__ float Ws[PKC][HH + 4];    // 32 x 68

    const int wsel = blockIdx.y;
    const float* W  = (wsel == 0) ? Wq : (wsel == 1) ? Wk : Wv;
    float* dst      = (wsel == 0) ? g_q : (wsel == 1) ? g_k : g_v;

    const int tid  = threadIdx.x;
    const int lane = tid & 31, warp = tid >> 5;
    const int r0   = warp * 16 + (lane >> 3) * 4;   // 4 local rows
    const int c0   = (lane & 7) * 8;                // 8 cols

    const size_t row0 = (size_t)blockIdx.x * PRT;

    float acc[4][8];
#pragma unroll
    for (int i = 0; i < 4; ++i)
#pragma unroll
        for (int j = 0; j < 8; ++j) acc[i][j] = 0.f;

    for (int kb = 0; kb < CC; kb += PKC) {
        if (kb) __syncthreads();
        // X tile: 64 rows x 32 floats = 512 float4
#pragma unroll
        for (int it = 0; it < 4; ++it) {
            int f = it * 128 + tid;
            int r = f >> 3, cf = (f & 7) * 4;
            *(float4*)&Xs[r][cf] = *(const float4*)&x[(row0 + r) * CC + kb + cf];
        }
        // W tile: 32 rows x 64 floats = 512 float4
#pragma unroll
        for (int it = 0; it < 4; ++it) {
            int f = it * 128 + tid;
            int r = f >> 4, cf = (f & 15) * 4;
            *(float4*)&Ws[r][cf] = *(const float4*)&W[(kb + r) * HH + cf];
        }
        __syncthreads();

#pragma unroll
        for (int kk = 0; kk < PKC; kk += 4) {
            float xr[4][4];
#pragma unroll
            for (int i = 0; i < 4; ++i) {
                float4 t = *(const float4*)&Xs[r0 + i][kk];
                xr[i][0] = t.x; xr[i][1] = t.y; xr[i][2] = t.z; xr[i][3] = t.w;
            }
#pragma unroll
            for (int m = 0; m < 4; ++m) {
                float4 wa = *(const float4*)&Ws[kk + m][c0];
                float4 wb = *(const float4*)&Ws[kk + m][c0 + 4];
                float wv[8] = {wa.x, wa.y, wa.z, wa.w, wb.x, wb.y, wb.z, wb.w};
#pragma unroll
                for (int i = 0; i < 4; ++i)
#pragma unroll
                    for (int j = 0; j < 8; ++j)
                        acc[i][j] = fmaf(xr[i][m], wv[j], acc[i][j]);
            }
        }
    }

#pragma unroll
    for (int i = 0; i < 4; ++i) {
        const size_t grow = row0 + r0 + i;
        float4 o1 = {acc[i][0], acc[i][1], acc[i][2], acc[i][3]};
        float4 o2 = {acc[i][4], acc[i][5], acc[i][6], acc[i][7]};
        *(float4*)&dst[grow * HH + c0]     = o1;
        *(float4*)&dst[grow * HH + c0 + 4] = o2;
    }
}

// ---------------------------------------------------------------------------
// Flash attention, register-blocked. CTA 128 threads, Q tile 64, K tile 64.
// Thread micro-tiles: scores 4q x 8k (k cols = kj + 8j), output 4q x 8d.
// Softmax state per q-row replicated across the 8 kj lanes (shfl reduce).
// ---------------------------------------------------------------------------
__global__ __launch_bounds__(128) void attn_kernel(
    float* __restrict__ out, float scale)
{
    extern __shared__ float sm[];
    float (*Qsh)[QSTR] = (float(*)[QSTR])sm;
    float (*Ksh)[KSTR] = (float(*)[KSTR])(sm + QT * QSTR);
    float (*Vsh)[VSTR] = (float(*)[VSTR])(sm + QT * QSTR + KT * KSTR);
    float (*Psh)[PSTR] = (float(*)[PSTR])(sm + QT * QSTR + KT * KSTR + KT * VSTR);

    const int b = blockIdx.y, qtile = blockIdx.x;
    const int tid  = threadIdx.x;
    const int lane = tid & 31, warp = tid >> 5;
    const int qi = lane >> 3, kj = lane & 7;
    const int qr0 = warp * 16 + qi * 4;     // 4 local q rows
    const int d0  = kj * 8;                 // 8 output dims

    // ---- load Q tile (64x64 = 1024 float4) ----
    const float* qg = g_q + ((size_t)b * TT + (size_t)qtile * QT) * HH;
#pragma unroll
    for (int it = 0; it < 8; ++it) {
        int f = it * 128 + tid;
        int r = f >> 4, cf = (f & 15) * 4;
        *(float4*)&Qsh[r][cf] = *(const float4*)&qg[r * HH + cf];
    }

    float acc[4][8];
#pragma unroll
    for (int i = 0; i < 4; ++i)
#pragma unroll
        for (int j = 0; j < 8; ++j) acc[i][j] = 0.f;
    float mrow[4] = {-1e30f, -1e30f, -1e30f, -1e30f};
    float lrow[4] = {0.f, 0.f, 0.f, 0.f};

    for (int kt = 0; kt <= qtile; ++kt) {
        const int kbase = kt * KT;
        if (kt) __syncthreads();             // prev PV done before overwrite
        // ---- load K,V tiles ----
        const float* kg = g_k + ((size_t)b * TT + kbase) * HH;
        const float* vg = g_v + ((size_t)b * TT + kbase) * HH;
#pragma unroll
        for (int it = 0; it < 8; ++it) {
            int f = it * 128 + tid;
            int r = f >> 4, cf = (f & 15) * 4;
            *(float4*)&Ksh[r][cf] = *(const float4*)&kg[r * HH + cf];
            *(float4*)&Vsh[r][cf] = *(const float4*)&vg[r * HH + cf];
        }
        __syncthreads();

        // ---- scores S[4][8], k col j -> local key kj + 8j ----
        float S[4][8];
#pragma unroll
        for (int i = 0; i < 4; ++i)
#pragma unroll
            for (int j = 0; j < 8; ++j) S[i][j] = 0.f;

#pragma unroll
        for (int d = 0; d < HH; d += 4) {
            float qr[4][4];
#pragma unroll
            for (int i = 0; i < 4; ++i) {
                float4 t = *(const float4*)&Qsh[qr0 + i][d];
                qr[i][0] = t.x; qr[i][1] = t.y; qr[i][2] = t.z; qr[i][3] = t.w;
            }
#pragma unroll
            for (int j = 0; j < 8; ++j) {
                float4 kf = *(const float4*)&Ksh[kj + 8 * j][d];
                float kv[4] = {kf.x, kf.y, kf.z, kf.w};
#pragma unroll
                for (int m = 0; m < 4; ++m)
#pragma unroll
                    for (int i = 0; i < 4; ++i)
                        S[i][j] = fmaf(qr[i][m], kv[m], S[i][j]);
            }
        }

        // ---- scale + causal mask (only diagonal tile can mask) ----
        float mt[4] = {-1e30f, -1e30f, -1e30f, -1e30f};
        const int tg0 = qtile * QT + qr0;
#pragma unroll
        for (int i = 0; i < 4; ++i)
#pragma unroll
            for (int j = 0; j < 8; ++j) {
                float s = S[i][j] * scale;
                if (kt == qtile && (kbase + kj + 8 * j) > (tg0 + i)) s = -1e30f;
                S[i][j] = s;
                mt[i] = fmaxf(mt[i], s);
            }
        // reduce row max across the 8 kj lanes
#pragma unroll
        for (int off = 1; off < 8; off <<= 1)
#pragma unroll
            for (int i = 0; i < 4; ++i)
                mt[i] = fmaxf(mt[i], __shfl_xor_sync(0xffffffffu, mt[i], off));

        float corr[4];
#pragma unroll
        for (int i = 0; i < 4; ++i) {
            float mn = fmaxf(mrow[i], mt[i]);
            corr[i] = __expf(mrow[i] - mn);
            mrow[i] = mn;
        }
        float ls[4] = {0.f, 0.f, 0.f, 0.f};
#pragma unroll
        for (int i = 0; i < 4; ++i)
#pragma unroll
            for (int j = 0; j < 8; ++j) {
                float p = __expf(S[i][j] - mrow[i]);
                ls[i] += p;
                Psh[qr0 + i][kj + 8 * j] = p;
            }
#pragma unroll
        for (int off = 1; off < 8; off <<= 1)
#pragma unroll
            for (int i = 0; i < 4; ++i)
                ls[i] += __shfl_xor_sync(0xffffffffu, ls[i], off);
#pragma unroll
        for (int i = 0; i < 4; ++i) {
            lrow[i] = lrow[i] * corr[i] + ls[i];
#pragma unroll
            for (int j = 0; j < 8; ++j) acc[i][j] *= corr[i];
        }
        __syncthreads();                     // P visible to all

        // ---- PV: out[4q][8d] += P[64q x 64k] @ V[64k x 64d] micro-tile ----
#pragma unroll
        for (int kk = 0; kk < KT; kk += 4) {
            float pr[4][4];
#pragma unroll
            for (int i = 0; i < 4; ++i) {
                float4 t = *(const float4*)&Psh[qr0 + i][kk];
                pr[i][0] = t.x; pr[i][1] = t.y; pr[i][2] = t.z; pr[i][3] = t.w;
            }
#pragma unroll
            for (int m = 0; m < 4; ++m) {
                float4 va = *(const float4*)&Vsh[kk + m][d0];
                float4 vb = *(const float4*)&Vsh[kk + m][d0 + 4];
                float vv[8] = {va.x, va.y, va.z, va.w, vb.x, vb.y, vb.z, vb.w};
#pragma unroll
                for (int i = 0; i < 4; ++i)
#pragma unroll
                    for (int j = 0; j < 8; ++j)
                        acc[i][j] = fmaf(pr[i][m], vv[j], acc[i][j]);
            }
        }
    }

    // ---- normalize + store ----
#pragma unroll
    for (int i = 0; i < 4; ++i) {
        const float inv = 1.f / lrow[i];
        const size_t t = (size_t)b * TT + (size_t)qtile * QT + qr0 + i;
        float4 o1 = {acc[i][0] * inv, acc[i][1] * inv, acc[i][2] * inv, acc[i][3] * inv};
        float4 o2 = {acc[i][4] * inv, acc[i][5] * inv, acc[i][6] * inv, acc[i][7] * inv};
        *(float4*)&out[t * HH + d0]     = o1;
        *(float4*)&out[t * HH + d0 + 4] = o2;
    }
}

// ---------------------------------------------------------------------------
extern "C" void kernel_launch(void* const* d_in, const int* in_sizes, int n_in,
                              void* d_out, int out_size)
{
    const float* x  = (const float*)d_in[0];
    const float* Wq = (const float*)d_in[1];
    const float* Wk = (const float*)d_in[2];
    const float* Wv = (const float*)d_in[3];
    float* out = (float*)d_out;

    const float scale = (float)pow(256.0, -0.666);

    cudaFuncSetAttribute(attn_kernel,
                         cudaFuncAttributeMaxDynamicSharedMemorySize, ATT_SMEM);

    dim3 pgrid((BB * TT) / PRT, 3);
    proj_kernel<<<pgrid, 128>>>(x, Wq, Wk, Wv);

    dim3 agrid(TT / QT, BB);
    attn_kernel<<<agrid, 128, ATT_SMEM>>>(out, scale);
}

// round 4
// speedup vs baseline: 3.4160x; 1.8431x over previous
#include <cuda_runtime.h>
#include <math.h>
#include <stdint.h>

#define BB 32
#define TT 1024
#define CC 256
#define HH 64

// ---------------- attention tiling ----------------
#define QT 64           // q rows per CTA (16 per warp)
#define KT 64           // keys per tile
#define KSTR 68         // Ksh padded stride (uint32)
#define VSTR 72         // Vsh padded stride
#define QSTR 68         // Qsh / Psh padded stride (aliased)
#define ATT_SMEM ((KT*KSTR + KT*VSTR + QT*QSTR) * 4)   // 53248 B

// ---------------- projection tiling ----------------
#define PRT 64
#define PKC 32

__device__ float g_q[BB * TT * HH];
__device__ float g_k[BB * TT * HH];
__device__ float g_v[BB * TT * HH];

// ---------------------------------------------------------------------------
__device__ __forceinline__ uint32_t f2tf(float f) {
    uint32_t u;
    asm("cvt.rna.tf32.f32 %0, %1;" : "=r"(u) : "f"(f));
    return u;
}

__device__ __forceinline__ void mma_tf32(float d[4], const uint32_t a[4],
                                         const uint32_t b0, const uint32_t b1) {
    asm("mma.sync.aligned.m16n8k8.row.col.f32.tf32.tf32.f32 "
        "{%0,%1,%2,%3}, {%4,%5,%6,%7}, {%8,%9}, {%0,%1,%2,%3};"
        : "+f"(d[0]), "+f"(d[1]), "+f"(d[2]), "+f"(d[3])
        : "r"(a[0]), "r"(a[1]), "r"(a[2]), "r"(a[3]), "r"(b0), "r"(b1));
}

// ---------------------------------------------------------------------------
// Projection GEMM (fp32 FFMA, unchanged from R3): X[32768,256] @ W[256,64].
// ---------------------------------------------------------------------------
__global__ __launch_bounds__(128) void proj_kernel(
    const float* __restrict__ x,
    const float* __restrict__ Wq,
    const float* __restrict__ Wk,
    const float* __restrict__ Wv)
{
    __shared__ float Xs[PRT][PKC + 4];
    __shared__ float Ws[PKC][HH + 4];

    const int wsel = blockIdx.y;
    const float* W  = (wsel == 0) ? Wq : (wsel == 1) ? Wk : Wv;
    float* dst      = (wsel == 0) ? g_q : (wsel == 1) ? g_k : g_v;

    const int tid  = threadIdx.x;
    const int lane = tid & 31, warp = tid >> 5;
    const int r0   = warp * 16 + (lane >> 3) * 4;
    const int c0   = (lane & 7) * 8;
    const size_t row0 = (size_t)blockIdx.x * PRT;

    float acc[4][8];
#pragma unroll
    for (int i = 0; i < 4; ++i)
#pragma unroll
        for (int j = 0; j < 8; ++j) acc[i][j] = 0.f;

    for (int kb = 0; kb < CC; kb += PKC) {
        if (kb) __syncthreads();
#pragma unroll
        for (int it = 0; it < 4; ++it) {
            int f = it * 128 + tid;
            int r = f >> 3, cf = (f & 7) * 4;
            *(float4*)&Xs[r][cf] = *(const float4*)&x[(row0 + r) * CC + kb + cf];
        }
#pragma unroll
        for (int it = 0; it < 4; ++it) {
            int f = it * 128 + tid;
            int r = f >> 4, cf = (f & 15) * 4;
            *(float4*)&Ws[r][cf] = *(const float4*)&W[(kb + r) * HH + cf];
        }
        __syncthreads();

#pragma unroll
        for (int kk = 0; kk < PKC; kk += 4) {
            float xr[4][4];
#pragma unroll
            for (int i = 0; i < 4; ++i) {
                float4 t = *(const float4*)&Xs[r0 + i][kk];
                xr[i][0] = t.x; xr[i][1] = t.y; xr[i][2] = t.z; xr[i][3] = t.w;
            }
#pragma unroll
            for (int m = 0; m < 4; ++m) {
                float4 wa = *(const float4*)&Ws[kk + m][c0];
                float4 wb = *(const float4*)&Ws[kk + m][c0 + 4];
                float wv[8] = {wa.x, wa.y, wa.z, wa.w, wb.x, wb.y, wb.z, wb.w};
#pragma unroll
                for (int i = 0; i < 4; ++i)
#pragma unroll
                    for (int j = 0; j < 8; ++j)
                        acc[i][j] = fmaf(xr[i][m], wv[j], acc[i][j]);
            }
        }
    }

#pragma unroll
    for (int i = 0; i < 4; ++i) {
        const size_t grow = row0 + r0 + i;
        float4 o1 = {acc[i][0], acc[i][1], acc[i][2], acc[i][3]};
        float4 o2 = {acc[i][4], acc[i][5], acc[i][6], acc[i][7]};
        *(float4*)&dst[grow * HH + c0]     = o1;
        *(float4*)&dst[grow * HH + c0 + 4] = o2;
    }
}

// ---------------------------------------------------------------------------
// Flash attention on tensor cores (mma.sync m16n8k8 tf32).
// 4 warps; warp w owns q rows [w*16, w*16+16). Q fragments preloaded in regs
// (scale folded). K/V tf32-converted at stage time. P staged through smem
// (aliases Q buffer), warp-local.
// ---------------------------------------------------------------------------
__global__ __launch_bounds__(128) void attn_kernel(
    float* __restrict__ out, float scale)
{
    extern __shared__ uint32_t smu[];
    uint32_t* Ks = smu;                       // [KT][KSTR]
    uint32_t* Vs = smu + KT * KSTR;           // [KT][VSTR]
    uint32_t* Qs = smu + KT * KSTR + KT * VSTR;  // [QT][QSTR], becomes Psh

    const int b = blockIdx.y, qtile = blockIdx.x;
    const int tid  = threadIdx.x;
    const int lane = tid & 31, warp = tid >> 5;
    const int r = lane >> 2, c = lane & 3;    // fragment row/col ids
    const int w16 = warp * 16;

    // ---- stage Q (scaled, tf32) ----
    {
        const float* qg = g_q + ((size_t)b * TT + (size_t)qtile * QT) * HH;
#pragma unroll
        for (int it = 0; it < 8; ++it) {
            int f = it * 128 + tid;
            int row = f >> 4, cf = (f & 15) * 4;
            float4 v = *(const float4*)&qg[row * HH + cf];
            uint4 u = {f2tf(v.x * scale), f2tf(v.y * scale),
                       f2tf(v.z * scale), f2tf(v.w * scale)};
            *(uint4*)&Qs[row * QSTR + cf] = u;
        }
    }
    __syncthreads();

    // ---- preload Q fragments: 8 k-steps x 4 regs ----
    uint32_t qf[8][4];
#pragma unroll
    for (int ks = 0; ks < 8; ++ks) {
        qf[ks][0] = Qs[(w16 + r)     * QSTR + 8 * ks + c];
        qf[ks][1] = Qs[(w16 + r + 8) * QSTR + 8 * ks + c];
        qf[ks][2] = Qs[(w16 + r)     * QSTR + 8 * ks + c + 4];
        qf[ks][3] = Qs[(w16 + r + 8) * QSTR + 8 * ks + c + 4];
    }
    __syncthreads();   // everyone done reading Qs before it is reused as Psh

    float O[8][4];
#pragma unroll
    for (int j = 0; j < 8; ++j)
#pragma unroll
        for (int i = 0; i < 4; ++i) O[j][i] = 0.f;
    float m0 = -1e30f, m1 = -1e30f, l0 = 0.f, l1 = 0.f;

    const int row0g = qtile * QT + w16 + r;   // global q row of frag row 0
    const int row1g = row0g + 8;

    for (int kt = 0; kt <= qtile; ++kt) {
        const int kbase = kt * KT;
        if (kt) __syncthreads();
        // ---- stage K,V (tf32) ----
        {
            const float* kg = g_k + ((size_t)b * TT + kbase) * HH;
            const float* vg = g_v + ((size_t)b * TT + kbase) * HH;
#pragma unroll
            for (int it = 0; it < 8; ++it) {
                int f = it * 128 + tid;
                int row = f >> 4, cf = (f & 15) * 4;
                float4 kv = *(const float4*)&kg[row * HH + cf];
                float4 vv = *(const float4*)&vg[row * HH + cf];
                uint4 ku = {f2tf(kv.x), f2tf(kv.y), f2tf(kv.z), f2tf(kv.w)};
                uint4 vu = {f2tf(vv.x), f2tf(vv.y), f2tf(vv.z), f2tf(vv.w)};
                *(uint4*)&Ks[row * KSTR + cf] = ku;
                *(uint4*)&Vs[row * VSTR + cf] = vu;
            }
        }
        __syncthreads();

        // ---- S = Q @ K^T : 8 n-tiles (keys), 8 k-steps (dims) ----
        float S[8][4];
#pragma unroll
        for (int j = 0; j < 8; ++j)
#pragma unroll
            for (int i = 0; i < 4; ++i) S[j][i] = 0.f;

#pragma unroll
        for (int ks = 0; ks < 8; ++ks) {
#pragma unroll
            for (int j = 0; j < 8; ++j) {
                uint32_t b0 = Ks[(8 * j + r) * KSTR + 8 * ks + c];
                uint32_t b1 = Ks[(8 * j + r) * KSTR + 8 * ks + c + 4];
                mma_tf32(S[j], qf[ks], b0, b1);
            }
        }

        // ---- causal mask (diagonal tile only) ----
        if (kt == qtile) {
#pragma unroll
            for (int j = 0; j < 8; ++j) {
                int col = kbase + 8 * j + 2 * c;
                if (col     > row0g) S[j][0] = -1e30f;
                if (col + 1 > row0g) S[j][1] = -1e30f;
                if (col     > row1g) S[j][2] = -1e30f;
                if (col + 1 > row1g) S[j][3] = -1e30f;
            }
        }

        // ---- online softmax (per-row, rows split across 4 lanes) ----
        float mt0 = -1e30f, mt1 = -1e30f;
#pragma unroll
        for (int j = 0; j < 8; ++j) {
            mt0 = fmaxf(mt0, fmaxf(S[j][0], S[j][1]));
            mt1 = fmaxf(mt1, fmaxf(S[j][2], S[j][3]));
        }
#pragma unroll
        for (int off = 1; off < 4; off <<= 1) {
            mt0 = fmaxf(mt0, __shfl_xor_sync(0xffffffffu, mt0, off));
            mt1 = fmaxf(mt1, __shfl_xor_sync(0xffffffffu, mt1, off));
        }
        const float mn0 = fmaxf(m0, mt0), mn1 = fmaxf(m1, mt1);
        const float cr0 = __expf(m0 - mn0), cr1 = __expf(m1 - mn1);
        m0 = mn0; m1 = mn1;

        float ls0 = 0.f, ls1 = 0.f;
#pragma unroll
        for (int j = 0; j < 8; ++j) {
            float p0 = __expf(S[j][0] - mn0);
            float p1 = __expf(S[j][1] - mn0);
            float p2 = __expf(S[j][2] - mn1);
            float p3 = __expf(S[j][3] - mn1);
            ls0 += p0 + p1; ls1 += p2 + p3;
            uint2 u01 = {f2tf(p0), f2tf(p1)};
            uint2 u23 = {f2tf(p2), f2tf(p3)};
            *(uint2*)&Qs[(w16 + r)     * QSTR + 8 * j + 2 * c] = u01;
            *(uint2*)&Qs[(w16 + r + 8) * QSTR + 8 * j + 2 * c] = u23;
        }
#pragma unroll
        for (int off = 1; off < 4; off <<= 1) {
            ls0 += __shfl_xor_sync(0xffffffffu, ls0, off);
            ls1 += __shfl_xor_sync(0xffffffffu, ls1, off);
        }
        l0 = l0 * cr0 + ls0;
        l1 = l1 * cr1 + ls1;
#pragma unroll
        for (int j = 0; j < 8; ++j) {
            O[j][0] *= cr0; O[j][1] *= cr0;
            O[j][2] *= cr1; O[j][3] *= cr1;
        }
        __syncwarp();   // P visible within the warp

        // ---- O += P @ V : 8 key-chunks x 8 d-tiles ----
#pragma unroll
        for (int ks = 0; ks < 8; ++ks) {
            uint32_t pf[4];
            pf[0] = Qs[(w16 + r)     * QSTR + 8 * ks + c];
            pf[1] = Qs[(w16 + r + 8) * QSTR + 8 * ks + c];
            pf[2] = Qs[(w16 + r)     * QSTR + 8 * ks + c + 4];
            pf[3] = Qs[(w16 + r + 8) * QSTR + 8 * ks + c + 4];
#pragma unroll
            for (int j = 0; j < 8; ++j) {
                uint32_t b0 = Vs[(8 * ks + c)     * VSTR + 8 * j + r];
                uint32_t b1 = Vs[(8 * ks + c + 4) * VSTR + 8 * j + r];
                mma_tf32(O[j], pf, b0, b1);
            }
        }
        __syncwarp();   // PV reads done before next tile overwrites Psh
    }

    // ---- normalize + store ----
    const float inv0 = 1.f / l0, inv1 = 1.f / l1;
    float* og = out + ((size_t)b * TT + (size_t)qtile * QT) * HH;
#pragma unroll
    for (int j = 0; j < 8; ++j) {
        float2 o0 = {O[j][0] * inv0, O[j][1] * inv0};
        float2 o1 = {O[j][2] * inv1, O[j][3] * inv1};
        *(float2*)&og[(w16 + r)     * HH + 8 * j + 2 * c] = o0;
        *(float2*)&og[(w16 + r + 8) * HH + 8 * j + 2 * c] = o1;
    }
}

// ---------------------------------------------------------------------------
extern "C" void kernel_launch(void* const* d_in, const int* in_sizes, int n_in,
                              void* d_out, int out_size)
{
    const float* x  = (const float*)d_in[0];
    const float* Wq = (const float*)d_in[1];
    const float* Wk = (const float*)d_in[2];
    const float* Wv = (const float*)d_in[3];
    float* out = (float*)d_out;

    const float scale = (float)pow(256.0, -0.666);

    cudaFuncSetAttribute(attn_kernel,
                         cudaFuncAttributeMaxDynamicSharedMemorySize, ATT_SMEM);

    dim3 pgrid((BB * TT) / PRT, 3);
    proj_kernel<<<pgrid, 128>>>(x, Wq, Wk, Wv);

    dim3 agrid(TT / QT, BB);
    attn_kernel<<<agrid, 128, ATT_SMEM>>>(out, scale);
}

// round 6
// speedup vs baseline: 3.6469x; 1.0676x over previous
#include <cuda_runtime.h>
#include <math.h>
#include <stdint.h>

#define BB 32
#define TT 1024
#define CC 256
#define HH 64

// ---------------- attention tiling ----------------
#define QT 64           // q rows per CTA (16 per warp)
#define KT 64           // keys per tile
#define KSTR 68         // Ksh padded stride (uint32)
#define VSTR 72         // Vsh padded stride
#define QSTR 68         // Qsh / Psh padded stride (aliased)
#define ATT_SMEM ((KT*KSTR + KT*VSTR + QT*QSTR) * 4)   // 53248 B

// ---------------- projection tiling (tf32 MMA, 3x split) ----------------
#define PRT 64          // rows per CTA
#define PKC 64          // k-chunk
#define XS2 66          // Xs stride in uint2 (hi,lo pairs)
#define WS2 66          // Ws stride in uint2
#define PROJ_SMEM ((PRT*XS2 + PKC*WS2) * 8)            // 67584 B

__device__ float g_q[BB * TT * HH];
__device__ float g_k[BB * TT * HH];
__device__ float g_v[BB * TT * HH];

// ---------------------------------------------------------------------------
__device__ __forceinline__ uint32_t f2tf(float f) {
    uint32_t u;
    asm("cvt.rna.tf32.f32 %0, %1;" : "=r"(u) : "f"(f));
    return u;
}

__device__ __forceinline__ void mma_tf32(float d[4], const uint32_t a[4],
                                         const uint32_t b0, const uint32_t b1) {
    asm("mma.sync.aligned.m16n8k8.row.col.f32.tf32.tf32.f32 "
        "{%0,%1,%2,%3}, {%4,%5,%6,%7}, {%8,%9}, {%0,%1,%2,%3};"
        : "+f"(d[0]), "+f"(d[1]), "+f"(d[2]), "+f"(d[3])
        : "r"(a[0]), "r"(a[1]), "r"(a[2]), "r"(a[3]), "r"(b0), "r"(b1));
}

// split fp32 -> (hi, lo) tf32 pair; hi + lo ~= x to ~2^-22
__device__ __forceinline__ uint2 split_tf(float x) {
    uint32_t hi = f2tf(x);
    uint32_t lo = f2tf(x - __uint_as_float(hi));
    return make_uint2(hi, lo);
}

// ---------------------------------------------------------------------------
// Projection GEMM on tensor cores, 3xTF32 split precision (fp32-accurate).
// X[32768,256] @ W[256,64], 3 matrices via blockIdx.y. CTA = 64x64 tile,
// 4 warps, each warp m=16 n=64. hi/lo interleaved as uint2 in smem:
// one LDS.64 per fragment reg pair feeds all 3 MMAs.
// ---------------------------------------------------------------------------
__global__ __launch_bounds__(128) void proj_kernel(
    const float* __restrict__ x,
    const float* __restrict__ Wq,
    const float* __restrict__ Wk,
    const float* __restrict__ Wv)
{
    extern __shared__ uint2 sm2[];
    uint2* Xs = sm2;                 // [PRT][XS2]  rows x k
    uint2* Ws = sm2 + PRT * XS2;     // [PKC][WS2]  k x n

    const int wsel = blockIdx.y;
    const float* W  = (wsel == 0) ? Wq : (wsel == 1) ? Wk : Wv;
    float* dst      = (wsel == 0) ? g_q : (wsel == 1) ? g_k : g_v;

    const int tid  = threadIdx.x;
    const int lane = tid & 31, warp = tid >> 5;
    const int r = lane >> 2, c = lane & 3;
    const int w16 = warp * 16;
    const size_t row0 = (size_t)blockIdx.x * PRT;

    float acc[8][4];
#pragma unroll
    for (int j = 0; j < 8; ++j)
#pragma unroll
        for (int i = 0; i < 4; ++i) acc[j][i] = 0.f;

    for (int kb = 0; kb < CC; kb += PKC) {
        if (kb) __syncthreads();
        // ---- stage X chunk: 64 rows x 64 k (1024 float4, 8 iters) ----
#pragma unroll
        for (int it = 0; it < 8; ++it) {
            int f = it * 128 + tid;
            int row = f >> 4, cf = (f & 15) * 4;
            float4 v = *(const float4*)&x[(row0 + row) * CC + kb + cf];
            uint2 s0 = split_tf(v.x), s1 = split_tf(v.y);
            uint2 s2 = split_tf(v.z), s3 = split_tf(v.w);
            uint4* p = (uint4*)&Xs[row * XS2 + cf];
            p[0] = make_uint4(s0.x, s0.y, s1.x, s1.y);
            p[1] = make_uint4(s2.x, s2.y, s3.x, s3.y);
        }
        // ---- stage W chunk: 64 k x 64 n ----
#pragma unroll
        for (int it = 0; it < 8; ++it) {
            int f = it * 128 + tid;
            int row = f >> 4, cf = (f & 15) * 4;
            float4 v = *(const float4*)&W[(kb + row) * HH + cf];
            uint2 s0 = split_tf(v.x), s1 = split_tf(v.y);
            uint2 s2 = split_tf(v.z), s3 = split_tf(v.w);
            uint4* p = (uint4*)&Ws[row * WS2 + cf];
            p[0] = make_uint4(s0.x, s0.y, s1.x, s1.y);
            p[1] = make_uint4(s2.x, s2.y, s3.x, s3.y);
        }
        __syncthreads();

        // ---- MMA: 8 k-steps x 8 n-tiles x 3 terms ----
#pragma unroll
        for (int ks = 0; ks < 8; ++ks) {
            uint2 a0 = Xs[(w16 + r)     * XS2 + 8 * ks + c];
            uint2 a1 = Xs[(w16 + r + 8) * XS2 + 8 * ks + c];
            uint2 a2 = Xs[(w16 + r)     * XS2 + 8 * ks + c + 4];
            uint2 a3 = Xs[(w16 + r + 8) * XS2 + 8 * ks + c + 4];
            uint32_t ahi[4] = {a0.x, a1.x, a2.x, a3.x};
            uint32_t alo[4] = {a0.y, a1.y, a2.y, a3.y};
#pragma unroll
            for (int j = 0; j < 8; ++j) {
                uint2 b0 = Ws[(8 * ks + c)     * WS2 + 8 * j + r];
                uint2 b1 = Ws[(8 * ks + c + 4) * WS2 + 8 * j + r];
                mma_tf32(acc[j], ahi, b0.x, b1.x);   // hi*hi
                mma_tf32(acc[j], ahi, b0.y, b1.y);   // hi*lo
                mma_tf32(acc[j], alo, b0.x, b1.x);   // lo*hi
            }
        }
    }

    // ---- store ----
#pragma unroll
    for (int j = 0; j < 8; ++j) {
        float2 o0 = {acc[j][0], acc[j][1]};
        float2 o1 = {acc[j][2], acc[j][3]};
        *(float2*)&dst[(row0 + w16 + r)     * HH + 8 * j + 2 * c] = o0;
        *(float2*)&dst[(row0 + w16 + r + 8) * HH + 8 * j + 2 * c] = o1;
    }
}

// ---------------------------------------------------------------------------
// Flash attention on tensor cores (mma.sync m16n8k8 tf32). Unchanged from R4
// except heavy-first CTA ordering (qtile reversed vs blockIdx.x).
// ---------------------------------------------------------------------------
__global__ __launch_bounds__(128) void attn_kernel(
    float* __restrict__ out, float scale)
{
    extern __shared__ uint32_t smu[];
    uint32_t* Ks = smu;                       // [KT][KSTR]
    uint32_t* Vs = smu + KT * KSTR;           // [KT][VSTR]
    uint32_t* Qs = smu + KT * KSTR + KT * VSTR;  // [QT][QSTR], becomes Psh

    const int b = blockIdx.y;
    const int qtile = gridDim.x - 1 - blockIdx.x;   // heavy tiles first
    const int tid  = threadIdx.x;
    const int lane = tid & 31, warp = tid >> 5;
    const int r = lane >> 2, c = lane & 3;
    const int w16 = warp * 16;

    // ---- stage Q (scaled, tf32) ----
    {
        const float* qg = g_q + ((size_t)b * TT + (size_t)qtile * QT) * HH;
#pragma unroll
        for (int it = 0; it < 8; ++it) {
            int f = it * 128 + tid;
            int row = f >> 4, cf = (f & 15) * 4;
            float4 v = *(const float4*)&qg[row * HH + cf];
            uint4 u = {f2tf(v.x * scale), f2tf(v.y * scale),
                       f2tf(v.z * scale), f2tf(v.w * scale)};
            *(uint4*)&Qs[row * QSTR + cf] = u;
        }
    }
    __syncthreads();

    uint32_t qf[8][4];
#pragma unroll
    for (int ks = 0; ks < 8; ++ks) {
        qf[ks][0] = Qs[(w16 + r)     * QSTR + 8 * ks + c];
        qf[ks][1] = Qs[(w16 + r + 8) * QSTR + 8 * ks + c];
        qf[ks][2] = Qs[(w16 + r)     * QSTR + 8 * ks + c + 4];
        qf[ks][3] = Qs[(w16 + r + 8) * QSTR + 8 * ks + c + 4];
    }
    __syncthreads();   // Qs free for reuse as Psh

    float O[8][4];
#pragma unroll
    for (int j = 0; j < 8; ++j)
#pragma unroll
        for (int i = 0; i < 4; ++i) O[j][i] = 0.f;
    float m0 = -1e30f, m1 = -1e30f, l0 = 0.f, l1 = 0.f;

    const int row0g = qtile * QT + w16 + r;
    const int row1g = row0g + 8;

    for (int kt = 0; kt <= qtile; ++kt) {
        const int kbase = kt * KT;
        if (kt) __syncthreads();
        {
            const float* kg = g_k + ((size_t)b * TT + kbase) * HH;
            const float* vg = g_v + ((size_t)b * TT + kbase) * HH;
#pragma unroll
            for (int it = 0; it < 8; ++it) {
                int f = it * 128 + tid;
                int row = f >> 4, cf = (f & 15) * 4;
                float4 kv = *(const float4*)&kg[row * HH + cf];
                float4 vv = *(const float4*)&vg[row * HH + cf];
                uint4 ku = {f2tf(kv.x), f2tf(kv.y), f2tf(kv.z), f2tf(kv.w)};
                uint4 vu = {f2tf(vv.x), f2tf(vv.y), f2tf(vv.z), f2tf(vv.w)};
                *(uint4*)&Ks[row * KSTR + cf] = ku;
                *(uint4*)&Vs[row * VSTR + cf] = vu;
            }
        }
        __syncthreads();

        float S[8][4];
#pragma unroll
        for (int j = 0; j < 8; ++j)
#pragma unroll
            for (int i = 0; i < 4; ++i) S[j][i] = 0.f;

#pragma unroll
        for (int ks = 0; ks < 8; ++ks) {
#pragma unroll
            for (int j = 0; j < 8; ++j) {
                uint32_t b0 = Ks[(8 * j + r) * KSTR + 8 * ks + c];
                uint32_t b1 = Ks[(8 * j + r) * KSTR + 8 * ks + c + 4];
                mma_tf32(S[j], qf[ks], b0, b1);
            }
        }

        if (kt == qtile) {
#pragma unroll
            for (int j = 0; j < 8; ++j) {
                int col = kbase + 8 * j + 2 * c;
                if (col     > row0g) S[j][0] = -1e30f;
                if (col + 1 > row0g) S[j][1] = -1e30f;
                if (col     > row1g) S[j][2] = -1e30f;
                if (col + 1 > row1g) S[j][3] = -1e30f;
            }
        }

        float mt0 = -1e30f, mt1 = -1e30f;
#pragma unroll
        for (int j = 0; j < 8; ++j) {
            mt0 = fmaxf(mt0, fmaxf(S[j][0], S[j][1]));
            mt1 = fmaxf(mt1, fmaxf(S[j][2], S[j][3]));
        }
#pragma unroll
        for (int off = 1; off < 4; off <<= 1) {
            mt0 = fmaxf(mt0, __shfl_xor_sync(0xffffffffu, mt0, off));
            mt1 = fmaxf(mt1, __shfl_xor_sync(0xffffffffu, mt1, off));
        }
        const float mn0 = fmaxf(m0, mt0), mn1 = fmaxf(m1, mt1);
        const float cr0 = __expf(m0 - mn0), cr1 = __expf(m1 - mn1);
        m0 = mn0; m1 = mn1;

        float ls0 = 0.f, ls1 = 0.f;
#pragma unroll
        for (int j = 0; j < 8; ++j) {
            float p0 = __expf(S[j][0] - mn0);
            float p1 = __expf(S[j][1] - mn0);
            float p2 = __expf(S[j][2] - mn1);
            float p3 = __expf(S[j][3] - mn1);
            ls0 += p0 + p1; ls1 += p2 + p3;
            uint2 u01 = {f2tf(p0), f2tf(p1)};
            uint2 u23 = {f2tf(p2), f2tf(p3)};
            *(uint2*)&Qs[(w16 + r)     * QSTR + 8 * j + 2 * c] = u01;
            *(uint2*)&Qs[(w16 + r + 8) * QSTR + 8 * j + 2 * c] = u23;
        }
#pragma unroll
        for (int off = 1; off < 4; off <<= 1) {
            ls0 += __shfl_xor_sync(0xffffffffu, ls0, off);
            ls1 += __shfl_xor_sync(0xffffffffu, ls1, off);
        }
        l0 = l0 * cr0 + ls0;
        l1 = l1 * cr1 + ls1;
#pragma unroll
        for (int j = 0; j < 8; ++j) {
            O[j][0] *= cr0; O[j][1] *= cr0;
            O[j][2] *= cr1; O[j][3] *= cr1;
        }
        __syncwarp();

#pragma unroll
        for (int ks = 0; ks < 8; ++ks) {
            uint32_t pf[4];
            pf[0] = Qs[(w16 + r)     * QSTR + 8 * ks + c];
            pf[1] = Qs[(w16 + r + 8) * QSTR + 8 * ks + c];
            pf[2] = Qs[(w16 + r)     * QSTR + 8 * ks + c + 4];
            pf[3] = Qs[(w16 + r + 8) * QSTR + 8 * ks + c + 4];
#pragma unroll
            for (int j = 0; j < 8; ++j) {
                uint32_t b0 = Vs[(8 * ks + c)     * VSTR + 8 * j + r];
                uint32_t b1 = Vs[(8 * ks + c + 4) * VSTR + 8 * j + r];
                mma_tf32(O[j], pf, b0, b1);
            }
        }
        __syncwarp();
    }

    const float inv0 = 1.f / l0, inv1 = 1.f / l1;
    float* og = out + ((size_t)b * TT + (size_t)qtile * QT) * HH;
#pragma unroll
    for (int j = 0; j < 8; ++j) {
        float2 o0 = {O[j][0] * inv0, O[j][1] * inv0};
        float2 o1 = {O[j][2] * inv1, O[j][3] * inv1};
        *(float2*)&og[(w16 + r)     * HH + 8 * j + 2 * c] = o0;
        *(float2*)&og[(w16 + r + 8) * HH + 8 * j + 2 * c] = o1;
    }
}

// ---------------------------------------------------------------------------
extern "C" void kernel_launch(void* const* d_in, const int* in_sizes, int n_in,
                              void* d_out, int out_size)
{
    const float* x  = (const float*)d_in[0];
    const float* Wq = (const float*)d_in[1];
    const float* Wk = (const float*)d_in[2];
    const float* Wv = (const float*)d_in[3];
    float* out = (float*)d_out;

    const float scale = (float)pow(256.0, -0.666);

    cudaFuncSetAttribute(proj_kernel,
                         cudaFuncAttributeMaxDynamicSharedMemorySize, PROJ_SMEM);
    cudaFuncSetAttribute(attn_kernel,
                         cudaFuncAttributeMaxDynamicSharedMemorySize, ATT_SMEM);

    dim3 pgrid((BB * TT) / PRT, 3);
    proj_kernel<<<pgrid, 128, PROJ_SMEM>>>(x, Wq, Wk, Wv);

    dim3 agrid(TT / QT, BB);
    attn_kernel<<<agrid, 128, ATT_SMEM>>>(out, scale);
}

// round 7
// speedup vs baseline: 4.9601x; 1.3601x over previous
#include <cuda_runtime.h>
#include <cuda_bf16.h>
#include <math.h>
#include <stdint.h>

#define BB 32
#define TT 1024
#define CC 256
#define HH 64

// ---------------- attention tiling ----------------
#define QT 64           // q rows per CTA (16 per warp)
#define KT 64           // keys per tile
#define KSTR 68         // Ksh padded stride (uint32)
#define VSTR 72         // Vsh padded stride
#define QSTR 68         // Qsh / Psh padded stride (aliased)
#define ATT_SMEM ((KT*KSTR + KT*VSTR + QT*QSTR) * 4)   // 53248 B

// ---------------- projection tiling (bf16x3 split MMA) ----------------
#define PRT 64          // rows per CTA
#define PKC 64          // k-chunk
#define XSTR 36         // pair-stride (32 bf16x2 pairs + 4 pad), ≡4 mod 32

__device__ float g_q[BB * TT * HH];
__device__ float g_k[BB * TT * HH];
__device__ float g_v[BB * TT * HH];

// ---------------------------------------------------------------------------
__device__ __forceinline__ uint32_t f2tf(float f) {
    uint32_t u;
    asm("cvt.rna.tf32.f32 %0, %1;" : "=r"(u) : "f"(f));
    return u;
}

__device__ __forceinline__ void mma_tf32(float d[4], const uint32_t a[4],
                                         const uint32_t b0, const uint32_t b1) {
    asm("mma.sync.aligned.m16n8k8.row.col.f32.tf32.tf32.f32 "
        "{%0,%1,%2,%3}, {%4,%5,%6,%7}, {%8,%9}, {%0,%1,%2,%3};"
        : "+f"(d[0]), "+f"(d[1]), "+f"(d[2]), "+f"(d[3])
        : "r"(a[0]), "r"(a[1]), "r"(a[2]), "r"(a[3]), "r"(b0), "r"(b1));
}

__device__ __forceinline__ void mma_bf16(float d[4], const uint32_t a[4],
                                         const uint32_t b0, const uint32_t b1) {
    asm("mma.sync.aligned.m16n8k16.row.col.f32.bf16.bf16.f32 "
        "{%0,%1,%2,%3}, {%4,%5,%6,%7}, {%8,%9}, {%0,%1,%2,%3};"
        : "+f"(d[0]), "+f"(d[1]), "+f"(d[2]), "+f"(d[3])
        : "r"(a[0]), "r"(a[1]), "r"(a[2]), "r"(a[3]), "r"(b0), "r"(b1));
}

__device__ __forceinline__ uint32_t pack_bf2(float a, float b) {
    __nv_bfloat162 t = __floats2bfloat162_rn(a, b);
    return *(uint32_t*)&t;
}
__device__ __forceinline__ float bf_hi(float x) {
    return __bfloat162float(__float2bfloat16_rn(x));
}

// ---------------------------------------------------------------------------
// Projection GEMM on tensor cores, bf16x3 split (hi+lo, ~16 mantissa bits).
// X[32768,256] @ W[256,64], 3 matrices via blockIdx.y. CTA = 64x64 tile,
// 4 warps each m=16 n=64. Hi/lo in separate smem planes, stride 36 (≡4 mod 32)
// => conflict-free (4r+c) fragment loads. W staged transposed to [n][k].
// ---------------------------------------------------------------------------
__global__ __launch_bounds__(128) void proj_kernel(
    const float* __restrict__ x,
    const float* __restrict__ Wq,
    const float* __restrict__ Wk,
    const float* __restrict__ Wv)
{
    __shared__ uint32_t Xh[PRT * XSTR], Xl[PRT * XSTR];   // rows x kpairs
    __shared__ uint32_t Wh[HH * XSTR],  Wl[HH * XSTR];    // n x kpairs

    const int wsel = blockIdx.y;
    const float* W  = (wsel == 0) ? Wq : (wsel == 1) ? Wk : Wv;
    float* dst      = (wsel == 0) ? g_q : (wsel == 1) ? g_k : g_v;

    const int tid  = threadIdx.x;
    const int lane = tid & 31, warp = tid >> 5;
    const int r = lane >> 2, c = lane & 3;
    const int w16 = warp * 16;
    const size_t row0 = (size_t)blockIdx.x * PRT;

    float acc[8][4];
#pragma unroll
    for (int j = 0; j < 8; ++j)
#pragma unroll
        for (int i = 0; i < 4; ++i) acc[j][i] = 0.f;

    for (int kb = 0; kb < CC; kb += PKC) {
        if (kb) __syncthreads();
        // ---- stage X chunk: 64 rows x 64 k (1024 float4 over 8 iters) ----
#pragma unroll
        for (int it = 0; it < 8; ++it) {
            int f = it * 128 + tid;
            int row = f >> 4, cf = (f & 15) * 4;        // k offset (floats)
            float4 v = *(const float4*)&x[(row0 + row) * CC + kb + cf];
            float hx = bf_hi(v.x), hy = bf_hi(v.y), hz = bf_hi(v.z), hw = bf_hi(v.w);
            uint2 hi = {pack_bf2(hx, hy), pack_bf2(hz, hw)};
            uint2 lo = {pack_bf2(v.x - hx, v.y - hy), pack_bf2(v.z - hz, v.w - hw)};
            int p = row * XSTR + cf / 2;                // pair index (8B aligned)
            *(uint2*)&Xh[p] = hi;
            *(uint2*)&Xl[p] = lo;
        }
        // ---- stage W chunk transposed: gmem [k][n] -> smem [n][kpair] ----
#pragma unroll
        for (int it = 0; it < 4; ++it) {
            int idx = it * 128 + tid;                   // 512 items
            int kp = idx >> 4, n0 = (idx & 15) * 4;     // kpair 0..31, 4 n cols
            float4 e = *(const float4*)&W[(kb + 2 * kp)     * HH + n0];
            float4 o = *(const float4*)&W[(kb + 2 * kp + 1) * HH + n0];
            float he[4] = {bf_hi(e.x), bf_hi(e.y), bf_hi(e.z), bf_hi(e.w)};
            float ho[4] = {bf_hi(o.x), bf_hi(o.y), bf_hi(o.z), bf_hi(o.w)};
            float ev[4] = {e.x, e.y, e.z, e.w}, ov[4] = {o.x, o.y, o.z, o.w};
#pragma unroll
            for (int i = 0; i < 4; ++i) {
                Wh[(n0 + i) * XSTR + kp] = pack_bf2(he[i], ho[i]);
                Wl[(n0 + i) * XSTR + kp] = pack_bf2(ev[i] - he[i], ov[i] - ho[i]);
            }
        }
        __syncthreads();

        // ---- MMA: 4 k16-steps x 8 n-tiles x 3 terms ----
#pragma unroll
        for (int ks = 0; ks < 4; ++ks) {
            const int kp0 = 8 * ks;
            uint32_t ah[4], al[4];
            ah[0] = Xh[(w16 + r)     * XSTR + kp0 + c];
            ah[1] = Xh[(w16 + r + 8) * XSTR + kp0 + c];
            ah[2] = Xh[(w16 + r)     * XSTR + kp0 + c + 4];
            ah[3] = Xh[(w16 + r + 8) * XSTR + kp0 + c + 4];
            al[0] = Xl[(w16 + r)     * XSTR + kp0 + c];
            al[1] = Xl[(w16 + r + 8) * XSTR + kp0 + c];
            al[2] = Xl[(w16 + r)     * XSTR + kp0 + c + 4];
            al[3] = Xl[(w16 + r + 8) * XSTR + kp0 + c + 4];
#pragma unroll
            for (int j = 0; j < 8; ++j) {
                const int nrow = (8 * j + r) * XSTR + kp0;
                uint32_t bh0 = Wh[nrow + c], bh1 = Wh[nrow + c + 4];
                uint32_t bl0 = Wl[nrow + c], bl1 = Wl[nrow + c + 4];
                mma_bf16(acc[j], ah, bh0, bh1);   // hi*hi
                mma_bf16(acc[j], ah, bl0, bl1);   // hi*lo
                mma_bf16(acc[j], al, bh0, bh1);   // lo*hi
            }
        }
    }

    // ---- store ----
#pragma unroll
    for (int j = 0; j < 8; ++j) {
        float2 o0 = {acc[j][0], acc[j][1]};
        float2 o1 = {acc[j][2], acc[j][3]};
        *(float2*)&dst[(row0 + w16 + r)     * HH + 8 * j + 2 * c] = o0;
        *(float2*)&dst[(row0 + w16 + r + 8) * HH + 8 * j + 2 * c] = o1;
    }
}

// ---------------------------------------------------------------------------
// Flash attention on tensor cores (mma.sync m16n8k8 tf32). Identical to the
// measured-77.8us R4 version (natural CTA order).
// ---------------------------------------------------------------------------
__global__ __launch_bounds__(128) void attn_kernel(
    float* __restrict__ out, float scale)
{
    extern __shared__ uint32_t smu[];
    uint32_t* Ks = smu;                       // [KT][KSTR]
    uint32_t* Vs = smu + KT * KSTR;           // [KT][VSTR]
    uint32_t* Qs = smu + KT * KSTR + KT * VSTR;  // [QT][QSTR], becomes Psh

    const int b = blockIdx.y, qtile = blockIdx.x;
    const int tid  = threadIdx.x;
    const int lane = tid & 31, warp = tid >> 5;
    const int r = lane >> 2, c = lane & 3;
    const int w16 = warp * 16;

    // ---- stage Q (scaled, tf32) ----
    {
        const float* qg = g_q + ((size_t)b * TT + (size_t)qtile * QT) * HH;
#pragma unroll
        for (int it = 0; it < 8; ++it) {
            int f = it * 128 + tid;
            int row = f >> 4, cf = (f & 15) * 4;
            float4 v = *(const float4*)&qg[row * HH + cf];
            uint4 u = {f2tf(v.x * scale), f2tf(v.y * scale),
                       f2tf(v.z * scale), f2tf(v.w * scale)};
            *(uint4*)&Qs[row * QSTR + cf] = u;
        }
    }
    __syncthreads();

    uint32_t qf[8][4];
#pragma unroll
    for (int ks = 0; ks < 8; ++ks) {
        qf[ks][0] = Qs[(w16 + r)     * QSTR + 8 * ks + c];
        qf[ks][1] = Qs[(w16 + r + 8) * QSTR + 8 * ks + c];
        qf[ks][2] = Qs[(w16 + r)     * QSTR + 8 * ks + c + 4];
        qf[ks][3] = Qs[(w16 + r + 8) * QSTR + 8 * ks + c + 4];
    }
    __syncthreads();   // Qs free for reuse as Psh

    float O[8][4];
#pragma unroll
    for (int j = 0; j < 8; ++j)
#pragma unroll
        for (int i = 0; i < 4; ++i) O[j][i] = 0.f;
    float m0 = -1e30f, m1 = -1e30f, l0 = 0.f, l1 = 0.f;

    const int row0g = qtile * QT + w16 + r;
    const int row1g = row0g + 8;

    for (int kt = 0; kt <= qtile; ++kt) {
        const int kbase = kt * KT;
        if (kt) __syncthreads();
        {
            const float* kg = g_k + ((size_t)b * TT + kbase) * HH;
            const float* vg = g_v + ((size_t)b * TT + kbase) * HH;
#pragma unroll
            for (int it = 0; it < 8; ++it) {
                int f = it * 128 + tid;
                int row = f >> 4, cf = (f & 15) * 4;
                float4 kv = *(const float4*)&kg[row * HH + cf];
                float4 vv = *(const float4*)&vg[row * HH + cf];
                uint4 ku = {f2tf(kv.x), f2tf(kv.y), f2tf(kv.z), f2tf(kv.w)};
                uint4 vu = {f2tf(vv.x), f2tf(vv.y), f2tf(vv.z), f2tf(vv.w)};
                *(uint4*)&Ks[row * KSTR + cf] = ku;
                *(uint4*)&Vs[row * VSTR + cf] = vu;
            }
        }
        __syncthreads();

        float S[8][4];
#pragma unroll
        for (int j = 0; j < 8; ++j)
#pragma unroll
            for (int i = 0; i < 4; ++i) S[j][i] = 0.f;

#pragma unroll
        for (int ks = 0; ks < 8; ++ks) {
#pragma unroll
            for (int j = 0; j < 8; ++j) {
                uint32_t b0 = Ks[(8 * j + r) * KSTR + 8 * ks + c];
                uint32_t b1 = Ks[(8 * j + r) * KSTR + 8 * ks + c + 4];
                mma_tf32(S[j], qf[ks], b0, b1);
            }
        }

        if (kt == qtile) {
#pragma unroll
            for (int j = 0; j < 8; ++j) {
                int col = kbase + 8 * j + 2 * c;
                if (col     > row0g) S[j][0] = -1e30f;
                if (col + 1 > row0g) S[j][1] = -1e30f;
                if (col     > row1g) S[j][2] = -1e30f;
                if (col + 1 > row1g) S[j][3] = -1e30f;
            }
        }

        float mt0 = -1e30f, mt1 = -1e30f;
#pragma unroll
        for (int j = 0; j < 8; ++j) {
            mt0 = fmaxf(mt0, fmaxf(S[j][0], S[j][1]));
            mt1 = fmaxf(mt1, fmaxf(S[j][2], S[j][3]));
        }
#pragma unroll
        for (int off = 1; off < 4; off <<= 1) {
            mt0 = fmaxf(mt0, __shfl_xor_sync(0xffffffffu, mt0, off));
            mt1 = fmaxf(mt1, __shfl_xor_sync(0xffffffffu, mt1, off));
        }
        const float mn0 = fmaxf(m0, mt0), mn1 = fmaxf(m1, mt1);
        const float cr0 = __expf(m0 - mn0), cr1 = __expf(m1 - mn1);
        m0 = mn0; m1 = mn1;

        float ls0 = 0.f, ls1 = 0.f;
#pragma unroll
        for (int j = 0; j < 8; ++j) {
            float p0 = __expf(S[j][0] - mn0);
            float p1 = __expf(S[j][1] - mn0);
            float p2 = __expf(S[j][2] - mn1);
            float p3 = __expf(S[j][3] - mn1);
            ls0 += p0 + p1; ls1 += p2 + p3;
            uint2 u01 = {f2tf(p0), f2tf(p1)};
            uint2 u23 = {f2tf(p2), f2tf(p3)};
            *(uint2*)&Qs[(w16 + r)     * QSTR + 8 * j + 2 * c] = u01;
            *(uint2*)&Qs[(w16 + r + 8) * QSTR + 8 * j + 2 * c] = u23;
        }
#pragma unroll
        for (int off = 1; off < 4; off <<= 1) {
            ls0 += __shfl_xor_sync(0xffffffffu, ls0, off);
            ls1 += __shfl_xor_sync(0xffffffffu, ls1, off);
        }
        l0 = l0 * cr0 + ls0;
        l1 = l1 * cr1 + ls1;
#pragma unroll
        for (int j = 0; j < 8; ++j) {
            O[j][0] *= cr0; O[j][1] *= cr0;
            O[j][2] *= cr1; O[j][3] *= cr1;
        }
        __syncwarp();

#pragma unroll
        for (int ks = 0; ks < 8; ++ks) {
            uint32_t pf[4];
            pf[0] = Qs[(w16 + r)     * QSTR + 8 * ks + c];
            pf[1] = Qs[(w16 + r + 8) * QSTR + 8 * ks + c];
            pf[2] = Qs[(w16 + r)     * QSTR + 8 * ks + c + 4];
            pf[3] = Qs[(w16 + r + 8) * QSTR + 8 * ks + c + 4];
#pragma unroll
            for (int j = 0; j < 8; ++j) {
                uint32_t b0 = Vs[(8 * ks + c)     * VSTR + 8 * j + r];
                uint32_t b1 = Vs[(8 * ks + c + 4) * VSTR + 8 * j + r];
                mma_tf32(O[j], pf, b0, b1);
            }
        }
        __syncwarp();
    }

    const float inv0 = 1.f / l0, inv1 = 1.f / l1;
    float* og = out + ((size_t)b * TT + (size_t)qtile * QT) * HH;
#pragma unroll
    for (int j = 0; j < 8; ++j) {
        float2 o0 = {O[j][0] * inv0, O[j][1] * inv0};
        float2 o1 = {O[j][2] * inv1, O[j][3] * inv1};
        *(float2*)&og[(w16 + r)     * HH + 8 * j + 2 * c] = o0;
        *(float2*)&og[(w16 + r + 8) * HH + 8 * j + 2 * c] = o1;
    }
}

// ---------------------------------------------------------------------------
extern "C" void kernel_launch(void* const* d_in, const int* in_sizes, int n_in,
                              void* d_out, int out_size)
{
    const float* x  = (const float*)d_in[0];
    const float* Wq = (const float*)d_in[1];
    const float* Wk = (const float*)d_in[2];
    const float* Wv = (const float*)d_in[3];
    float* out = (float*)d_out;

    const float scale = (float)pow(256.0, -0.666);

    cudaFuncSetAttribute(attn_kernel,
                         cudaFuncAttributeMaxDynamicSharedMemorySize, ATT_SMEM);

    dim3 pgrid((BB * TT) / PRT, 3);
    proj_kernel<<<pgrid, 128>>>(x, Wq, Wk, Wv);

    dim3 agrid(TT / QT, BB);
    attn_kernel<<<agrid, 128, ATT_SMEM>>>(out, scale);
}